// round 1
// baseline (speedup 1.0000x reference)
#include <cuda_runtime.h>
#include <cuda_bf16.h>

#define N_NODES 50000
#define N_EDGES 800000
#define IN_F    256
#define OUT_F   64

// Scratch: projected + src-norm-scaled node features [N_NODES, OUT_F]
__device__ float g_hw[(size_t)N_NODES * OUT_F];

// ---------------------------------------------------------------------------
// Zero the accumulator (d_out is poisoned 0xAA before timing)
// ---------------------------------------------------------------------------
__global__ void zero_kernel(float4* __restrict__ out) {
    int i = blockIdx.x * blockDim.x + threadIdx.x;
    if (i < (N_NODES * OUT_F) / 4)
        out[i] = make_float4(0.f, 0.f, 0.f, 0.f);
}

// ---------------------------------------------------------------------------
// GEMM + fold norm[src]:  g_hw[n, :] = (h[n, :] @ W) * norm[n]
// Block tile: 64 rows x 64 cols, K chunked by 64. 256 threads, 4x4 reg tile.
// ---------------------------------------------------------------------------
__global__ __launch_bounds__(256) void gemm_norm_kernel(
    const float* __restrict__ h,
    const float* __restrict__ w,
    const float* __restrict__ norm)
{
    __shared__ float hs[64][64];  // [row][k]
    __shared__ float ws[64][64];  // [k][col]

    const int t   = threadIdx.x;
    const int cx  = t & 15;   // col group: cols 4*cx .. 4*cx+3
    const int ry  = t >> 4;   // row group: rows 4*ry .. 4*ry+3
    const int row0 = blockIdx.x * 64;

    float acc[4][4];
#pragma unroll
    for (int i = 0; i < 4; i++)
#pragma unroll
        for (int j = 0; j < 4; j++) acc[i][j] = 0.f;

    for (int kk = 0; kk < IN_F; kk += 64) {
        // Stage W chunk: w[(kk+k)*OUT_F + c], 4096 floats, coalesced float4
        {
            const float4* wsrc = (const float4*)(w + (size_t)kk * OUT_F);
            float4* wdst = (float4*)&ws[0][0];
#pragma unroll
            for (int i = 0; i < 4; i++)
                wdst[t + 256 * i] = wsrc[t + 256 * i];
        }
        // Stage H chunk: 64 rows x 64 k, 4 threads per row, float4 loads
        {
            const int r = t >> 2;
            const int q = t & 3;
            const int grow = row0 + r;
#pragma unroll
            for (int i = 0; i < 4; i++) {
                const int f4 = q + 4 * i;  // float4 index within row (0..15)
                float4 v = make_float4(0.f, 0.f, 0.f, 0.f);
                if (grow < N_NODES)
                    v = *(const float4*)(h + (size_t)grow * IN_F + kk + f4 * 4);
                *(float4*)&hs[r][f4 * 4] = v;
            }
        }
        __syncthreads();

#pragma unroll
        for (int k = 0; k < 64; k += 4) {
            float4 a0 = *(const float4*)&hs[4 * ry + 0][k];
            float4 a1 = *(const float4*)&hs[4 * ry + 1][k];
            float4 a2 = *(const float4*)&hs[4 * ry + 2][k];
            float4 a3 = *(const float4*)&hs[4 * ry + 3][k];
            float4 b0 = *(const float4*)&ws[k + 0][4 * cx];
            float4 b1 = *(const float4*)&ws[k + 1][4 * cx];
            float4 b2 = *(const float4*)&ws[k + 2][4 * cx];
            float4 b3 = *(const float4*)&ws[k + 3][4 * cx];

#define ROW_FMA(i, a)                                                   \
            acc[i][0] = fmaf(a.x, b0.x, acc[i][0]);                     \
            acc[i][1] = fmaf(a.x, b0.y, acc[i][1]);                     \
            acc[i][2] = fmaf(a.x, b0.z, acc[i][2]);                     \
            acc[i][3] = fmaf(a.x, b0.w, acc[i][3]);                     \
            acc[i][0] = fmaf(a.y, b1.x, acc[i][0]);                     \
            acc[i][1] = fmaf(a.y, b1.y, acc[i][1]);                     \
            acc[i][2] = fmaf(a.y, b1.z, acc[i][2]);                     \
            acc[i][3] = fmaf(a.y, b1.w, acc[i][3]);                     \
            acc[i][0] = fmaf(a.z, b2.x, acc[i][0]);                     \
            acc[i][1] = fmaf(a.z, b2.y, acc[i][1]);                     \
            acc[i][2] = fmaf(a.z, b2.z, acc[i][2]);                     \
            acc[i][3] = fmaf(a.z, b2.w, acc[i][3]);                     \
            acc[i][0] = fmaf(a.w, b3.x, acc[i][0]);                     \
            acc[i][1] = fmaf(a.w, b3.y, acc[i][1]);                     \
            acc[i][2] = fmaf(a.w, b3.z, acc[i][2]);                     \
            acc[i][3] = fmaf(a.w, b3.w, acc[i][3]);

            ROW_FMA(0, a0)
            ROW_FMA(1, a1)
            ROW_FMA(2, a2)
            ROW_FMA(3, a3)
#undef ROW_FMA
        }
        __syncthreads();
    }

    // Epilogue: scale by norm[row], write to scratch
#pragma unroll
    for (int i = 0; i < 4; i++) {
        const int grow = row0 + 4 * ry + i;
        if (grow < N_NODES) {
            const float nv = norm[grow];
            float4 v = make_float4(acc[i][0] * nv, acc[i][1] * nv,
                                   acc[i][2] * nv, acc[i][3] * nv);
            *(float4*)(g_hw + (size_t)grow * OUT_F + 4 * cx) = v;
        }
    }
}

// ---------------------------------------------------------------------------
// Edge scatter: out[dst] += g_hw[src]   (16 threads per edge, float4 red)
// ---------------------------------------------------------------------------
__global__ __launch_bounds__(256) void scatter_kernel(
    const int* __restrict__ src,
    const int* __restrict__ dst,
    float* __restrict__ out)
{
    const int t = blockIdx.x * blockDim.x + threadIdx.x;
    const int e = t >> 4;
    if (e >= N_EDGES) return;
    const int c = (t & 15) << 2;

    const int s = __ldg(src + e);
    const int d = __ldg(dst + e);

    const float4 v = *(const float4*)(g_hw + (size_t)s * OUT_F + c);
    float* p = out + (size_t)d * OUT_F + c;
    asm volatile("red.global.add.v4.f32 [%0], {%1, %2, %3, %4};"
                 :: "l"(p), "f"(v.x), "f"(v.y), "f"(v.z), "f"(v.w)
                 : "memory");
}

// ---------------------------------------------------------------------------
// Finalize: out = relu(out * norm[row] + bias)
// ---------------------------------------------------------------------------
__global__ __launch_bounds__(256) void finalize_kernel(
    float* __restrict__ out,
    const float* __restrict__ norm,
    const float* __restrict__ bias)
{
    const int i = blockIdx.x * blockDim.x + threadIdx.x;  // over N_NODES*16
    if (i >= N_NODES * (OUT_F / 4)) return;
    const int row = i >> 4;
    const int c = (i & 15) << 2;

    const float nv = __ldg(norm + row);
    float4 v = *(float4*)(out + (size_t)row * OUT_F + c);
    const float4 b = *(const float4*)(bias + c);
    v.x = fmaxf(fmaf(v.x, nv, b.x), 0.f);
    v.y = fmaxf(fmaf(v.y, nv, b.y), 0.f);
    v.z = fmaxf(fmaf(v.z, nv, b.z), 0.f);
    v.w = fmaxf(fmaf(v.w, nv, b.w), 0.f);
    *(float4*)(out + (size_t)row * OUT_F + c) = v;
}

// ---------------------------------------------------------------------------
extern "C" void kernel_launch(void* const* d_in, const int* in_sizes, int n_in,
                              void* d_out, int out_size)
{
    const float* h      = (const float*)d_in[0];
    const float* norm   = (const float*)d_in[1];
    const int*   src    = (const int*)d_in[2];
    const int*   dst    = (const int*)d_in[3];
    const float* weight = (const float*)d_in[4];
    const float* bias   = (const float*)d_in[5];
    float* out = (float*)d_out;

    // 1) zero accumulator (d_out is poisoned)
    {
        int n4 = (N_NODES * OUT_F) / 4;
        zero_kernel<<<(n4 + 255) / 256, 256>>>((float4*)out);
    }
    // 2) projection + fold norm[src]
    {
        int blocks = (N_NODES + 63) / 64;  // 782
        gemm_norm_kernel<<<blocks, 256>>>(h, weight, norm);
    }
    // 3) edge scatter-add
    {
        long threads = (long)N_EDGES * 16;
        scatter_kernel<<<(int)((threads + 255) / 256), 256>>>(src, dst, out);
    }
    // 4) finalize: scale by norm[dst], bias, relu
    {
        int n = N_NODES * (OUT_F / 4);
        finalize_kernel<<<(n + 255) / 256, 256>>>(out, norm, bias);
    }
}

// round 2
// speedup vs baseline: 1.0547x; 1.0547x over previous
#include <cuda_runtime.h>
#include <cuda_bf16.h>

#define N_NODES 50000
#define N_EDGES 800000
#define IN_F    256
#define OUT_F   64
#define NB1     196   // ceil(50000/256) blocks for scan

// Scratch (device globals: allocation-guard compliant)
__device__ float g_hw[(size_t)N_NODES * OUT_F];   // projected*norm features
__device__ int   g_deg[N_NODES];                  // in-degree histogram
__device__ int   g_start[N_NODES];                // CSR row starts
__device__ int   g_cursor[N_NODES];               // fill cursors
__device__ int   g_bsum[256];                     // per-block sums for scan
__device__ int   g_boff[256];                     // scanned block offsets
__device__ int   g_esrc[N_EDGES];                 // src ids bucketed by dst

// ---------------------------------------------------------------------------
// CSR build step 1: zero the histogram (device globals persist across calls)
// ---------------------------------------------------------------------------
__global__ void zero_deg_kernel() {
    int i = blockIdx.x * blockDim.x + threadIdx.x;
    if (i < N_NODES) g_deg[i] = 0;
}

// CSR build step 2: in-degree histogram
__global__ void hist_kernel(const int* __restrict__ dst) {
    int e = blockIdx.x * blockDim.x + threadIdx.x;
    if (e < N_EDGES) atomicAdd(&g_deg[dst[e]], 1);
}

// CSR build step 3a: per-block sums
__global__ __launch_bounds__(256) void scan1_kernel() {
    __shared__ int sh[256];
    int i = blockIdx.x * 256 + threadIdx.x;
    int v = (i < N_NODES) ? g_deg[i] : 0;
    sh[threadIdx.x] = v;
    __syncthreads();
    for (int s = 128; s > 0; s >>= 1) {
        if (threadIdx.x < s) sh[threadIdx.x] += sh[threadIdx.x + s];
        __syncthreads();
    }
    if (threadIdx.x == 0) g_bsum[blockIdx.x] = sh[0];
}

// CSR build step 3b: exclusive scan of block sums (single block)
__global__ __launch_bounds__(256) void scan2_kernel() {
    __shared__ int sh[256];
    int t = threadIdx.x;
    int v = (t < NB1) ? g_bsum[t] : 0;
    sh[t] = v;
    __syncthreads();
    for (int off = 1; off < 256; off <<= 1) {
        int x = (t >= off) ? sh[t - off] : 0;
        __syncthreads();
        sh[t] += x;
        __syncthreads();
    }
    g_boff[t] = sh[t] - v;  // exclusive
}

// CSR build step 3c: per-element exclusive scan + block offset
__global__ __launch_bounds__(256) void scan3_kernel() {
    __shared__ int sh[256];
    int t = threadIdx.x;
    int i = blockIdx.x * 256 + t;
    int v = (i < N_NODES) ? g_deg[i] : 0;
    sh[t] = v;
    __syncthreads();
    for (int off = 1; off < 256; off <<= 1) {
        int x = (t >= off) ? sh[t - off] : 0;
        __syncthreads();
        sh[t] += x;
        __syncthreads();
    }
    if (i < N_NODES) {
        int excl = sh[t] - v + g_boff[blockIdx.x];
        g_start[i]  = excl;
        g_cursor[i] = excl;
    }
}

// CSR build step 4: bucket src ids by dst
__global__ void fill_kernel(const int* __restrict__ src,
                            const int* __restrict__ dst) {
    int e = blockIdx.x * blockDim.x + threadIdx.x;
    if (e >= N_EDGES) return;
    int d = dst[e];
    int slot = atomicAdd(&g_cursor[d], 1);
    g_esrc[slot] = src[e];
}

// ---------------------------------------------------------------------------
// GEMM + fold norm[src]:  g_hw[n, :] = (h[n, :] @ W) * norm[n]
// Block tile: 64 rows x 64 cols, K chunked by 64. 256 threads, 4x4 reg tile.
// ---------------------------------------------------------------------------
__global__ __launch_bounds__(256) void gemm_norm_kernel(
    const float* __restrict__ h,
    const float* __restrict__ w,
    const float* __restrict__ norm)
{
    __shared__ float hs[64][64];  // [row][k]
    __shared__ float ws[64][64];  // [k][col]

    const int t   = threadIdx.x;
    const int cx  = t & 15;   // col group: cols 4*cx .. 4*cx+3
    const int ry  = t >> 4;   // row group: rows 4*ry .. 4*ry+3
    const int row0 = blockIdx.x * 64;

    float acc[4][4];
#pragma unroll
    for (int i = 0; i < 4; i++)
#pragma unroll
        for (int j = 0; j < 4; j++) acc[i][j] = 0.f;

    for (int kk = 0; kk < IN_F; kk += 64) {
        {
            const float4* wsrc = (const float4*)(w + (size_t)kk * OUT_F);
            float4* wdst = (float4*)&ws[0][0];
#pragma unroll
            for (int i = 0; i < 4; i++)
                wdst[t + 256 * i] = wsrc[t + 256 * i];
        }
        {
            const int r = t >> 2;
            const int q = t & 3;
            const int grow = row0 + r;
#pragma unroll
            for (int i = 0; i < 4; i++) {
                const int f4 = q + 4 * i;
                float4 v = make_float4(0.f, 0.f, 0.f, 0.f);
                if (grow < N_NODES)
                    v = *(const float4*)(h + (size_t)grow * IN_F + kk + f4 * 4);
                *(float4*)&hs[r][f4 * 4] = v;
            }
        }
        __syncthreads();

#pragma unroll
        for (int k = 0; k < 64; k += 4) {
            float4 a0 = *(const float4*)&hs[4 * ry + 0][k];
            float4 a1 = *(const float4*)&hs[4 * ry + 1][k];
            float4 a2 = *(const float4*)&hs[4 * ry + 2][k];
            float4 a3 = *(const float4*)&hs[4 * ry + 3][k];
            float4 b0 = *(const float4*)&ws[k + 0][4 * cx];
            float4 b1 = *(const float4*)&ws[k + 1][4 * cx];
            float4 b2 = *(const float4*)&ws[k + 2][4 * cx];
            float4 b3 = *(const float4*)&ws[k + 3][4 * cx];

#define ROW_FMA(i, a)                                                   \
            acc[i][0] = fmaf(a.x, b0.x, acc[i][0]);                     \
            acc[i][1] = fmaf(a.x, b0.y, acc[i][1]);                     \
            acc[i][2] = fmaf(a.x, b0.z, acc[i][2]);                     \
            acc[i][3] = fmaf(a.x, b0.w, acc[i][3]);                     \
            acc[i][0] = fmaf(a.y, b1.x, acc[i][0]);                     \
            acc[i][1] = fmaf(a.y, b1.y, acc[i][1]);                     \
            acc[i][2] = fmaf(a.y, b1.z, acc[i][2]);                     \
            acc[i][3] = fmaf(a.y, b1.w, acc[i][3]);                     \
            acc[i][0] = fmaf(a.z, b2.x, acc[i][0]);                     \
            acc[i][1] = fmaf(a.z, b2.y, acc[i][1]);                     \
            acc[i][2] = fmaf(a.z, b2.z, acc[i][2]);                     \
            acc[i][3] = fmaf(a.z, b2.w, acc[i][3]);                     \
            acc[i][0] = fmaf(a.w, b3.x, acc[i][0]);                     \
            acc[i][1] = fmaf(a.w, b3.y, acc[i][1]);                     \
            acc[i][2] = fmaf(a.w, b3.z, acc[i][2]);                     \
            acc[i][3] = fmaf(a.w, b3.w, acc[i][3]);

            ROW_FMA(0, a0)
            ROW_FMA(1, a1)
            ROW_FMA(2, a2)
            ROW_FMA(3, a3)
#undef ROW_FMA
        }
        __syncthreads();
    }

#pragma unroll
    for (int i = 0; i < 4; i++) {
        const int grow = row0 + 4 * ry + i;
        if (grow < N_NODES) {
            const float nv = norm[grow];
            float4 v = make_float4(acc[i][0] * nv, acc[i][1] * nv,
                                   acc[i][2] * nv, acc[i][3] * nv);
            *(float4*)(g_hw + (size_t)grow * OUT_F + 4 * cx) = v;
        }
    }
}

// ---------------------------------------------------------------------------
// Aggregate: one warp per dst node. Each lane owns 2 output floats.
// out[d] = relu( (sum_{e in bucket(d)} g_hw[src_e]) * norm[d] + bias )
// No atomics, no pre-zero, fused epilogue.
// ---------------------------------------------------------------------------
__global__ __launch_bounds__(256) void aggregate_kernel(
    const float* __restrict__ norm,
    const float* __restrict__ bias,
    float* __restrict__ out)
{
    const int warp = (blockIdx.x * 256 + threadIdx.x) >> 5;
    const int lane = threadIdx.x & 31;
    if (warp >= N_NODES) return;

    const int start = g_start[warp];
    const int deg   = g_deg[warp];
    const float2* __restrict__ hw2 = (const float2*)g_hw;

    float ax = 0.f, ay = 0.f;
    int j = 0;
    for (; j + 1 < deg; j += 2) {
        const int s0 = __ldg(g_esrc + start + j);
        const int s1 = __ldg(g_esrc + start + j + 1);
        const float2 v0 = hw2[(size_t)s0 * 32 + lane];
        const float2 v1 = hw2[(size_t)s1 * 32 + lane];
        ax += v0.x + v1.x;
        ay += v0.y + v1.y;
    }
    if (j < deg) {
        const int s0 = __ldg(g_esrc + start + j);
        const float2 v0 = hw2[(size_t)s0 * 32 + lane];
        ax += v0.x;
        ay += v0.y;
    }

    const float nv = __ldg(norm + warp);
    const float2 b = ((const float2*)bias)[lane];
    float2 r;
    r.x = fmaxf(fmaf(ax, nv, b.x), 0.f);
    r.y = fmaxf(fmaf(ay, nv, b.y), 0.f);
    ((float2*)out)[(size_t)warp * 32 + lane] = r;
}

// ---------------------------------------------------------------------------
extern "C" void kernel_launch(void* const* d_in, const int* in_sizes, int n_in,
                              void* d_out, int out_size)
{
    const float* h      = (const float*)d_in[0];
    const float* norm   = (const float*)d_in[1];
    const int*   src    = (const int*)d_in[2];
    const int*   dst    = (const int*)d_in[3];
    const float* weight = (const float*)d_in[4];
    const float* bias   = (const float*)d_in[5];
    float* out = (float*)d_out;

    // Projection (independent of CSR build)
    gemm_norm_kernel<<<(N_NODES + 63) / 64, 256>>>(h, weight, norm);

    // CSR build
    zero_deg_kernel<<<NB1, 256>>>();
    hist_kernel<<<(N_EDGES + 255) / 256, 256>>>(dst);
    scan1_kernel<<<NB1, 256>>>();
    scan2_kernel<<<1, 256>>>();
    scan3_kernel<<<NB1, 256>>>();
    fill_kernel<<<(N_EDGES + 255) / 256, 256>>>(src, dst);

    // Aggregation + fused epilogue (norm[dst], bias, relu)
    {
        long threads = (long)N_NODES * 32;
        aggregate_kernel<<<(int)((threads + 255) / 256), 256>>>(norm, bias, out);
    }
}